// round 1
// baseline (speedup 1.0000x reference)
#include <cuda_runtime.h>

// ============================================================================
// VLunchboxMHSA — linear-attention reassociation (no softmax in reference!)
//
//   h = x @ qkv; q = h[...,0,:], k = h[...,1,:]
//   attn = (q kᵀ) * SCALE ; res = attn @ v ; out = res @ proj
//
// Reassociated:
//   K[b,m,h,d]   = Σ_c x[b,m,c] qkv[c, h*128+64+d]              (kernel 1)
//   KV[b,h,d,l]  = Σ_m K[b,m,h,d] v[m,h,l]                       (kernel 2)
//   W2[b,h,d,e]  = SCALE Σ_l KV[b,h,d,l] proj[h*64+l, e]         (kernel 3)
//   Wfin[b,c,e]  = Σ_{h,d} qkv[c, h*128+d] W2[b,h,d,e]           (kernel 4)
//   out[b,n,e]   = Σ_c x[b,n,c] Wfin[b,c,e]                      (kernel 5)
// ============================================================================

#define SCALE 0.125f

// Scratch (static device globals — no allocation allowed)
__device__ float d_K[4 * 2048 * 512];    // [b, m, h*64+d]   16 MB
__device__ float d_KV[32 * 64 * 64];     // [bh, d, l]
__device__ float d_W2[4 * 512 * 64];     // [b, h*64+d, e]
__device__ float d_Wfin[4 * 512 * 64];   // [b, c, e]

// ---------------------------------------------------------------------------
// k0: zero the atomic-accumulated scratch + output
// ---------------------------------------------------------------------------
__global__ void k0_zero(float* __restrict__ out) {
    int idx = blockIdx.x * blockDim.x + threadIdx.x;  // grid covers 524288
    if (idx < 32 * 64 * 64)  d_KV[idx]   = 0.f;
    if (idx < 4 * 512 * 64)  d_Wfin[idx] = 0.f;
    if (idx < 4 * 2048 * 64) out[idx]    = 0.f;
}

// ---------------------------------------------------------------------------
// k1: K = x @ Wk   (M=8192, N=512, K=512), Wk gathered from qkv columns
//     128x128 block tile, 256 threads, 8x8 per thread
// ---------------------------------------------------------------------------
__global__ __launch_bounds__(256) void k1_kproj(const float* __restrict__ x,
                                                const float* __restrict__ qkv) {
    __shared__ float As[16][132];  // As[k][m], padded
    __shared__ float Bs[16][128];  // Bs[k][n]

    const int tid = threadIdx.x;
    const int bm = blockIdx.y * 128;
    const int bn = blockIdx.x * 128;
    const int ty = tid >> 4;   // 0..15
    const int tx = tid & 15;   // 0..15

    float acc[8][8];
#pragma unroll
    for (int i = 0; i < 8; i++)
#pragma unroll
        for (int j = 0; j < 8; j++) acc[i][j] = 0.f;

    for (int k0 = 0; k0 < 512; k0 += 16) {
        // load A tile: 128 rows x 16 k-cols (transposed into smem)
#pragma unroll
        for (int i = 0; i < 2; i++) {
            int pos = tid + i * 256;          // 0..511
            int r   = pos >> 2;               // 0..127
            int c4  = (pos & 3) << 2;         // 0,4,8,12
            float4 a = *(const float4*)(x + ((size_t)(bm + r) << 9) + k0 + c4);
            As[c4 + 0][r] = a.x; As[c4 + 1][r] = a.y;
            As[c4 + 2][r] = a.z; As[c4 + 3][r] = a.w;
        }
        // load B tile (gathered Wk): 16 k-rows x 128 n-cols
#pragma unroll
        for (int i = 0; i < 2; i++) {
            int pos = tid + i * 256;
            int kr  = pos >> 5;               // 0..15
            int nc  = (pos & 31) << 2;        // 0..124
            int n   = bn + nc;
            int col = ((n >> 6) << 7) + 64 + (n & 63);   // k-part column
            *(float4*)&Bs[kr][nc] =
                *(const float4*)(qkv + ((size_t)(k0 + kr) << 10) + col);
        }
        __syncthreads();

#pragma unroll
        for (int kk = 0; kk < 16; kk++) {
            float a[8], b[8];
            *(float4*)(a)     = *(float4*)&As[kk][ty * 8];
            *(float4*)(a + 4) = *(float4*)&As[kk][ty * 8 + 4];
            *(float4*)(b)     = *(float4*)&Bs[kk][tx * 8];
            *(float4*)(b + 4) = *(float4*)&Bs[kk][tx * 8 + 4];
#pragma unroll
            for (int i = 0; i < 8; i++)
#pragma unroll
                for (int j = 0; j < 8; j++) acc[i][j] += a[i] * b[j];
        }
        __syncthreads();
    }

#pragma unroll
    for (int i = 0; i < 8; i++) {
        float* dst = d_K + ((size_t)(bm + ty * 8 + i) << 9) + bn + tx * 8;
#pragma unroll
        for (int j = 0; j < 8; j += 4) {
            *(float4*)(dst + j) =
                make_float4(acc[i][j], acc[i][j + 1], acc[i][j + 2], acc[i][j + 3]);
        }
    }
}

// ---------------------------------------------------------------------------
// k2: KV[bh] += K[b,mrange,h,:]^T @ v[mrange,h,:]   (split over m, atomicAdd)
//     grid (32 bh, 16 m-splits), 256 threads, 4x4 per thread on a 64x64 tile
// ---------------------------------------------------------------------------
__global__ __launch_bounds__(256) void k2_kv(const float* __restrict__ v) {
    const int bh = blockIdx.x;          // 0..31
    const int b  = bh >> 3, h = bh & 7;
    const int ms = blockIdx.y;          // 0..15

    __shared__ float Ks[16][64];
    __shared__ float Vs[16][64];

    const int tid = threadIdx.x;
    const int td  = (tid >> 4) << 2;    // d offset 0..60
    const int tl  = (tid & 15) << 2;    // l offset 0..60
    const int lr  = tid >> 4;           // load row 0..15
    const int lc  = (tid & 15) << 2;    // load col

    float acc[4][4] = {};

    const float* Kb = d_K + (size_t)b * 2048 * 512 + h * 64;
    const float* Vb = v + h * 64;

    for (int m0 = ms * 128; m0 < ms * 128 + 128; m0 += 16) {
        *(float4*)&Ks[lr][lc] = *(const float4*)(Kb + (size_t)(m0 + lr) * 512 + lc);
        *(float4*)&Vs[lr][lc] = *(const float4*)(Vb + (size_t)(m0 + lr) * 512 + lc);
        __syncthreads();
#pragma unroll
        for (int mm = 0; mm < 16; mm++) {
            float kd[4], vl[4];
            *(float4*)kd = *(float4*)&Ks[mm][td];
            *(float4*)vl = *(float4*)&Vs[mm][tl];
#pragma unroll
            for (int i = 0; i < 4; i++)
#pragma unroll
                for (int j = 0; j < 4; j++) acc[i][j] += kd[i] * vl[j];
        }
        __syncthreads();
    }

    float* KVp = d_KV + (size_t)bh * 4096;
#pragma unroll
    for (int i = 0; i < 4; i++)
#pragma unroll
        for (int j = 0; j < 4; j++)
            atomicAdd(&KVp[(td + i) * 64 + tl + j], acc[i][j]);
}

// ---------------------------------------------------------------------------
// k3: W2[b, h*64+d, e] = SCALE * Σ_l KV[bh,d,l] * proj[h*64+l, e]
//     grid 32 blocks (one per bh), 64x64 output, K=64 in smem
// ---------------------------------------------------------------------------
__global__ __launch_bounds__(256) void k3_w2(const float* __restrict__ proj) {
    const int bh = blockIdx.x;
    const int b  = bh >> 3, h = bh & 7;

    __shared__ float KVs[64][64];
    __shared__ float Ps[64][64];

    const int tid = threadIdx.x;
#pragma unroll
    for (int i = 0; i < 4; i++) {
        int pos = tid + i * 256;
        int r   = pos >> 4;
        int c   = (pos & 15) << 2;
        *(float4*)&KVs[r][c] = *(const float4*)(d_KV + (size_t)bh * 4096 + r * 64 + c);
        *(float4*)&Ps[r][c]  = *(const float4*)(proj + (size_t)(h * 64 + r) * 64 + c);
    }
    __syncthreads();

    const int td = (tid >> 4) << 2;
    const int te = (tid & 15) << 2;
    float acc[4][4] = {};

#pragma unroll 8
    for (int l = 0; l < 64; l++) {
        float a[4], bb[4];
#pragma unroll
        for (int i = 0; i < 4; i++) a[i] = KVs[td + i][l];
        *(float4*)bb = *(float4*)&Ps[l][te];
#pragma unroll
        for (int i = 0; i < 4; i++)
#pragma unroll
            for (int j = 0; j < 4; j++) acc[i][j] += a[i] * bb[j];
    }

#pragma unroll
    for (int i = 0; i < 4; i++)
#pragma unroll
        for (int j = 0; j < 4; j++)
            d_W2[((size_t)b * 512 + h * 64 + td + i) * 64 + te + j] = SCALE * acc[i][j];
}

// ---------------------------------------------------------------------------
// k4: Wfin[b,c,e] += Σ_j Wq[c,j] W2[b,j,e], Wq gathered from qkv q-columns
//     grid (4 b, 8 c-tiles of 64, 4 j-splits of 128), atomicAdd
// ---------------------------------------------------------------------------
__global__ __launch_bounds__(256) void k4_wfin(const float* __restrict__ qkv) {
    const int b  = blockIdx.x;
    const int ct = blockIdx.y;   // 0..7
    const int js = blockIdx.z;   // 0..3

    __shared__ float Aq[16][68]; // Aq[j][c], padded
    __shared__ float Bs[16][64]; // W2[j][e]

    const int tid = threadIdx.x;
    const int tc  = (tid >> 4) << 2;
    const int te  = (tid & 15) << 2;
    float acc[4][4] = {};

    for (int j0 = js * 128; j0 < js * 128 + 128; j0 += 16) {
        {
            int r  = tid >> 2;            // 0..63  (c-row)
            int c4 = (tid & 3) << 2;      // j offset 0,4,8,12
            int c  = ct * 64 + r;
            int j  = j0 + c4;
            float4 a = *(const float4*)(qkv + ((size_t)c << 10) +
                                        ((j >> 6) << 7) + (j & 63));  // q-part column
            Aq[c4 + 0][r] = a.x; Aq[c4 + 1][r] = a.y;
            Aq[c4 + 2][r] = a.z; Aq[c4 + 3][r] = a.w;
        }
        {
            int jr = tid >> 4;
            int e4 = (tid & 15) << 2;
            *(float4*)&Bs[jr][e4] =
                *(const float4*)(d_W2 + ((size_t)b * 512 + j0 + jr) * 64 + e4);
        }
        __syncthreads();
#pragma unroll
        for (int jj = 0; jj < 16; jj++) {
            float a[4], bb[4];
            *(float4*)a  = *(float4*)&Aq[jj][tc];
            *(float4*)bb = *(float4*)&Bs[jj][te];
#pragma unroll
            for (int i = 0; i < 4; i++)
#pragma unroll
                for (int j = 0; j < 4; j++) acc[i][j] += a[i] * bb[j];
        }
        __syncthreads();
    }

#pragma unroll
    for (int i = 0; i < 4; i++)
#pragma unroll
        for (int j = 0; j < 4; j++)
            atomicAdd(&d_Wfin[((size_t)b * 512 + ct * 64 + tc + i) * 64 + te + j],
                      acc[i][j]);
}

// ---------------------------------------------------------------------------
// k5: out[b,n,e] += Σ_c x[b,n,c] Wfin[b,c,e]
//     grid (4 b, 32 n-tiles of 64, 4 c-splits of 128), atomicAdd into out
// ---------------------------------------------------------------------------
__global__ __launch_bounds__(256) void k5_out(const float* __restrict__ x,
                                              float* __restrict__ out) {
    const int b  = blockIdx.x;
    const int nt = blockIdx.y;   // 0..31
    const int ks = blockIdx.z;   // 0..3

    __shared__ float Xs[16][68]; // Xs[c][n], padded
    __shared__ float Ws[16][64]; // Wfin[c][e]

    const int tid = threadIdx.x;
    const int tn  = (tid >> 4) << 2;
    const int te  = (tid & 15) << 2;
    float acc[4][4] = {};

    for (int c0 = ks * 128; c0 < ks * 128 + 128; c0 += 16) {
        {
            int r  = tid >> 2;           // 0..63 (n-row)
            int c4 = (tid & 3) << 2;     // c offset
            float4 a = *(const float4*)(x + ((size_t)(b * 2048 + nt * 64 + r) << 9) +
                                        c0 + c4);
            Xs[c4 + 0][r] = a.x; Xs[c4 + 1][r] = a.y;
            Xs[c4 + 2][r] = a.z; Xs[c4 + 3][r] = a.w;
        }
        {
            int cr = tid >> 4;
            int e4 = (tid & 15) << 2;
            *(float4*)&Ws[cr][e4] =
                *(const float4*)(d_Wfin + ((size_t)b * 512 + c0 + cr) * 64 + e4);
        }
        __syncthreads();
#pragma unroll
        for (int cc = 0; cc < 16; cc++) {
            float a[4], bb[4];
            *(float4*)a  = *(float4*)&Xs[cc][tn];
            *(float4*)bb = *(float4*)&Ws[cc][te];
#pragma unroll
            for (int i = 0; i < 4; i++)
#pragma unroll
                for (int j = 0; j < 4; j++) acc[i][j] += a[i] * bb[j];
        }
        __syncthreads();
    }

#pragma unroll
    for (int i = 0; i < 4; i++)
#pragma unroll
        for (int j = 0; j < 4; j++)
            atomicAdd(&out[((size_t)(b * 2048 + nt * 64 + tn + i)) * 64 + te + j],
                      acc[i][j]);
}

// ---------------------------------------------------------------------------
extern "C" void kernel_launch(void* const* d_in, const int* in_sizes, int n_in,
                              void* d_out, int out_size) {
    const float* x    = (const float*)d_in[0];  // [4, 2048, 512]
    const float* v    = (const float*)d_in[1];  // [2048, 8, 64]
    const float* qkv  = (const float*)d_in[2];  // [512, 1024]
    const float* proj = (const float*)d_in[3];  // [512, 64]
    float* out = (float*)d_out;                 // [4, 2048, 64]

    k0_zero<<<2048, 256>>>(out);
    k1_kproj<<<dim3(4, 64), 256>>>(x, qkv);
    k2_kv<<<dim3(32, 16), 256>>>(v);
    k3_w2<<<32, 256>>>(proj);
    k4_wfin<<<dim3(4, 8, 4), 256>>>(qkv);
    k5_out<<<dim3(4, 32, 4), 256>>>(x, out);
}